// round 8
// baseline (speedup 1.0000x reference)
#include <cuda_runtime.h>
#include <math.h>

// Problem shape (fixed by setup_inputs): B=8, Sq=Sk=1024, D=64, N_QUBITS=4.
#define B_     8
#define SQ_    1024
#define SK_    1024
#define D_     64
#define NQ_    4
#define NROWS_ (B_ * SQ_)          // 8192 rows per side

// Scratch:
//  g_G : per-qubit 2x2 Gram entries [n*4 + i*2 + j]  (theta only, 16 floats)
//  g_q : AoS [row][8]  per qubit (0.5*sin(pi t), 0.5*cos(pi t))
//  g_k : SoA [b][comp(8)][SK] per qubit (G00*S+G01*C, G10*S+G11*C)
// per-qubit factor = 0.5 + q0*k0 + q1*k1   (G fully folded into k in prep)
__device__ float g_G[16];
__device__ float g_q[NROWS_ * 8];
__device__ float g_k[B_ * 8 * SK_];

// ---------------------------------------------------------------------------
// packed f32x2 helpers
// ---------------------------------------------------------------------------
__device__ __forceinline__ unsigned long long f2fma(unsigned long long a,
                                                    unsigned long long b,
                                                    unsigned long long c)
{
    unsigned long long d;
    asm("fma.rn.f32x2 %0, %1, %2, %3;" : "=l"(d) : "l"(a), "l"(b), "l"(c));
    return d;
}
__device__ __forceinline__ unsigned long long f2mul(unsigned long long a,
                                                    unsigned long long b)
{
    unsigned long long d;
    asm("mul.rn.f32x2 %0, %1, %2;" : "=l"(d) : "l"(a), "l"(b));
    return d;
}
__device__ __forceinline__ unsigned long long f2dup(float v)
{
    unsigned long long d;
    asm("mov.b64 %0, {%1, %1};" : "=l"(d) : "f"(v));
    return d;
}

#define HALF2_ 0x3F0000003F000000ULL   // {0.5f, 0.5f}

// Bloch-rotation columns of M = Rz(om)*Ry(th)*Rz(phi):  u = M*ex, v = M*ez
__device__ __forceinline__ void uv_cols(float phi, float th, float om,
                                        float u[3], float v[3])
{
    float sp, cp, st, ct, so, co;
    sincosf(phi, &sp, &cp);
    sincosf(th,  &st, &ct);
    sincosf(om,  &so, &co);
    float ax = ct * cp, ay = sp, az = -st * cp;
    u[0] = ax * co - ay * so;
    u[1] = ax * so + ay * co;
    u[2] = az;
    v[0] = st * co;
    v[1] = st * so;
    v[2] = ct;
}

// ---------------------------------------------------------------------------
// Kernel A: the 16 Gram entries (one thread each)
// ---------------------------------------------------------------------------
__global__ void g_kernel(const float* __restrict__ theta_q,
                         const float* __restrict__ theta_k)
{
    int tid = threadIdx.x;
    if (tid >= 16) return;
    int n = tid >> 2, i = (tid >> 1) & 1, j = tid & 1;
    float uq[3], vq[3], uk[3], vk[3];
    uv_cols(theta_q[3 * n], theta_q[3 * n + 1], theta_q[3 * n + 2], uq, vq);
    uv_cols(theta_k[3 * n], theta_k[3 * n + 1], theta_k[3 * n + 2], uk, vk);
    const float* a  = i ? vq : uq;
    const float* bb = j ? vk : uk;
    g_G[tid] = a[0] * bb[0] + a[1] * bb[1] + a[2] * bb[2];
}

// ---------------------------------------------------------------------------
// Kernel B: per-row (S,C); k-side premultiplied by G (read from g_G).
// rows [0,8192) -> query side, [8192,16384) -> key side
// ---------------------------------------------------------------------------
__global__ void prep_kernel(const float* __restrict__ query,
                            const float* __restrict__ key)
{
    int row = blockIdx.x * blockDim.x + threadIdx.x;
    if (row >= 2 * NROWS_) return;

    bool isQ = row < NROWS_;
    int r = isQ ? row : row - NROWS_;

    // first 4 of the 64 features, 16B-aligned (row stride 256B)
    float4 xv = *(const float4*)((isQ ? query : key) + (size_t)r * D_);
    float xs[4] = {xv.x, xv.y, xv.z, xv.w};

    float S[NQ_], C[NQ_];
#pragma unroll
    for (int n = 0; n < NQ_; n++) {
        float t = tanhf(xs[n]);
        sincospif(t, &S[n], &C[n]);
    }

    if (isQ) {
        float out8[8];
#pragma unroll
        for (int n = 0; n < NQ_; n++) {
            out8[2 * n]     = 0.5f * S[n];
            out8[2 * n + 1] = 0.5f * C[n];
        }
        float* d = g_q + (size_t)r * 8;
        *(float4*)(d)     = *(const float4*)(out8);
        *(float4*)(d + 4) = *(const float4*)(out8 + 4);
    } else {
        int b = r >> 10;           // SK_ = 1024
        int s = r & (SK_ - 1);
#pragma unroll
        for (int n = 0; n < NQ_; n++) {
            float G00 = g_G[n * 4 + 0], G01 = g_G[n * 4 + 1];
            float G10 = g_G[n * 4 + 2], G11 = g_G[n * 4 + 3];
            g_k[((size_t)(b * 8 + 2 * n))     * SK_ + s] = fmaf(G00, S[n], G01 * C[n]);
            g_k[((size_t)(b * 8 + 2 * n + 1)) * SK_ + s] = fmaf(G10, S[n], G11 * C[n]);
        }
    }
}

// ---------------------------------------------------------------------------
// Kernel C: out[b][q][k] = 0.5 + 0.5 * prod_n (0.5 + q0*k0 + q1*k1)
// Tile: 128 q x 128 k, 256 threads; thread owns 4 k-cols as packed pairs,
// iterates 16 q-rows JAMMED 2 AT A TIME (two independent LDS->FMA->STG
// chains per iteration for 2x ILP).  regs budget 3 blocks/SM (~85).
// ---------------------------------------------------------------------------
#define TQ 128
#define TK 128

__global__ __launch_bounds__(256, 3) void pair_kernel(float* __restrict__ out)
{
    __shared__ __align__(16) float  sq[TQ][8];         // raw q rows
    __shared__ __align__(16) float4 skv[8][TK / 4];    // SoA k tile (G-folded)

    int b  = blockIdx.z;
    int q0 = blockIdx.y * TQ;
    int k0 = blockIdx.x * TK;
    int tid = threadIdx.x;

    // fill skv: 8 comps * 32 float4 = 256 float4 -> one per thread
    {
        int comp = tid >> 5, off = tid & 31;
        skv[comp][off] =
            *(const float4*)(g_k + ((size_t)(b * 8 + comp)) * SK_ + k0 + off * 4);
    }
    // fill sq: TQ*8 floats = 256 float4 -> one per thread
    ((float4*)sq)[tid] =
        ((const float4*)(g_q + (size_t)(b * SQ_ + q0) * 8))[tid];
    __syncthreads();

    int k4 = tid & 31;     // this thread's 4 consecutive k columns
    int qg = tid >> 5;     // q group: rows qg*16 .. qg*16+15

    // k tile: 8 components x (2 packed pairs) in registers
    ulonglong2 kd[8];
#pragma unroll
    for (int j = 0; j < 8; j++)
        kd[j] = *(const ulonglong2*)&skv[j][k4];

    float* obase = out + ((size_t)(b * SQ_ + q0 + qg * 16) * SK_) + k0 + k4 * 4;

#pragma unroll
    for (int rr = 0; rr < 8; rr++) {
        int ra = qg * 16 + 2 * rr;

        // two rows' q vectors (4 warp-uniform LDS.128)
        float4 a0 = *(const float4*)&sq[ra][0];
        float4 a1 = *(const float4*)&sq[ra][4];
        float4 b0 = *(const float4*)&sq[ra + 1][0];
        float4 b1 = *(const float4*)&sq[ra + 1][4];

        unsigned long long qa[8], qb[8];
        qa[0] = f2dup(a0.x); qa[1] = f2dup(a0.y);
        qa[2] = f2dup(a0.z); qa[3] = f2dup(a0.w);
        qa[4] = f2dup(a1.x); qa[5] = f2dup(a1.y);
        qa[6] = f2dup(a1.z); qa[7] = f2dup(a1.w);
        qb[0] = f2dup(b0.x); qb[1] = f2dup(b0.y);
        qb[2] = f2dup(b0.z); qb[3] = f2dup(b0.w);
        qb[4] = f2dup(b1.x); qb[5] = f2dup(b1.y);
        qb[6] = f2dup(b1.z); qb[7] = f2dup(b1.w);

        unsigned long long ta0[NQ_], ta1[NQ_], tb0[NQ_], tb1[NQ_];
#pragma unroll
        for (int n = 0; n < NQ_; n++) {
            ta0[n] = f2fma(qa[2 * n], kd[2 * n].x,
                     f2fma(qa[2 * n + 1], kd[2 * n + 1].x, HALF2_));
            ta1[n] = f2fma(qa[2 * n], kd[2 * n].y,
                     f2fma(qa[2 * n + 1], kd[2 * n + 1].y, HALF2_));
            tb0[n] = f2fma(qb[2 * n], kd[2 * n].x,
                     f2fma(qb[2 * n + 1], kd[2 * n + 1].x, HALF2_));
            tb1[n] = f2fma(qb[2 * n], kd[2 * n].y,
                     f2fma(qb[2 * n + 1], kd[2 * n + 1].y, HALF2_));
        }
        unsigned long long pa0 = f2mul(f2mul(ta0[0], ta0[1]), f2mul(ta0[2], ta0[3]));
        unsigned long long pa1 = f2mul(f2mul(ta1[0], ta1[1]), f2mul(ta1[2], ta1[3]));
        unsigned long long pb0 = f2mul(f2mul(tb0[0], tb0[1]), f2mul(tb0[2], tb0[3]));
        unsigned long long pb1 = f2mul(f2mul(tb1[0], tb1[1]), f2mul(tb1[2], tb1[3]));
        pa0 = f2fma(pa0, HALF2_, HALF2_);
        pa1 = f2fma(pa1, HALF2_, HALF2_);
        pb0 = f2fma(pb0, HALF2_, HALF2_);
        pb1 = f2fma(pb1, HALF2_, HALF2_);

        float* oa = obase + (size_t)(2 * rr) * SK_;
        asm volatile("st.global.v2.b64 [%0], {%1, %2};"
                     :: "l"(oa), "l"(pa0), "l"(pa1) : "memory");
        asm volatile("st.global.v2.b64 [%0], {%1, %2};"
                     :: "l"(oa + SK_), "l"(pb0), "l"(pb1) : "memory");
    }
}

extern "C" void kernel_launch(void* const* d_in, const int* in_sizes, int n_in,
                              void* d_out, int out_size)
{
    const float* query   = (const float*)d_in[0];
    const float* key     = (const float*)d_in[1];
    const float* theta_q = (const float*)d_in[2];
    const float* theta_k = (const float*)d_in[3];
    float* out = (float*)d_out;

    g_kernel<<<1, 16>>>(theta_q, theta_k);
    prep_kernel<<<(2 * NROWS_ + 255) / 256, 256>>>(query, key);

    dim3 grid(SK_ / TK, SQ_ / TQ, B_);
    pair_kernel<<<grid, 256>>>(out);
}

// round 9
// speedup vs baseline: 1.0867x; 1.0867x over previous
#include <cuda_runtime.h>
#include <math.h>

// Problem shape (fixed by setup_inputs): B=8, Sq=Sk=1024, D=64, N_QUBITS=4.
#define B_     8
#define SQ_    1024
#define SK_    1024
#define D_     64
#define NQ_    4
#define NROWS_ (B_ * SQ_)          // 8192 rows per side

// Scratch:
//  g_q : AoS [row][8]  per qubit (0.5*sin(pi t), 0.5*cos(pi t))
//  g_k : SoA [b][comp(8)][SK] per qubit (G00*S+G01*C, G10*S+G11*C)
// per-qubit factor = 0.5 + q0*k0 + q1*k1   (G fully folded into k in prep;
// G itself is recomputed redundantly per prep block in smem — no extra launch)
__device__ float g_q[NROWS_ * 8];
__device__ float g_k[B_ * 8 * SK_];

// ---------------------------------------------------------------------------
// packed f32x2 helpers
// ---------------------------------------------------------------------------
__device__ __forceinline__ unsigned long long f2fma(unsigned long long a,
                                                    unsigned long long b,
                                                    unsigned long long c)
{
    unsigned long long d;
    asm("fma.rn.f32x2 %0, %1, %2, %3;" : "=l"(d) : "l"(a), "l"(b), "l"(c));
    return d;
}
__device__ __forceinline__ unsigned long long f2mul(unsigned long long a,
                                                    unsigned long long b)
{
    unsigned long long d;
    asm("mul.rn.f32x2 %0, %1, %2;" : "=l"(d) : "l"(a), "l"(b));
    return d;
}
__device__ __forceinline__ unsigned long long f2dup(float v)
{
    unsigned long long d;
    asm("mov.b64 %0, {%1, %1};" : "=l"(d) : "f"(v));
    return d;
}

#define HALF2_ 0x3F0000003F000000ULL   // {0.5f, 0.5f}

// Bloch-rotation columns of M = Rz(om)*Ry(th)*Rz(phi):  u = M*ex, v = M*ez
__device__ __forceinline__ void uv_cols(float phi, float th, float om,
                                        float u[3], float v[3])
{
    float sp, cp, st, ct, so, co;
    sincosf(phi, &sp, &cp);
    sincosf(th,  &st, &ct);
    sincosf(om,  &so, &co);
    float ax = ct * cp, ay = sp, az = -st * cp;
    u[0] = ax * co - ay * so;
    u[1] = ax * so + ay * co;
    u[2] = az;
    v[0] = st * co;
    v[1] = st * so;
    v[2] = ct;
}

// ---------------------------------------------------------------------------
// Phase 1: per-row (S,C); k-side premultiplied by G.
// G is computed at BLOCK scope (threads 0..15, redundant per block, smem) —
// overlapped across blocks, so it adds no serial launch.
// rows [0,8192) -> query side, [8192,16384) -> key side
// ---------------------------------------------------------------------------
__global__ void prep_kernel(const float* __restrict__ query,
                            const float* __restrict__ key,
                            const float* __restrict__ theta_q,
                            const float* __restrict__ theta_k)
{
    __shared__ float sG[16];

    int tid = threadIdx.x;
    int row = blockIdx.x * blockDim.x + tid;

    if (tid < 16) {
        int n = tid >> 2, i = (tid >> 1) & 1, j = tid & 1;
        float uq[3], vq[3], uk[3], vk[3];
        uv_cols(theta_q[3 * n], theta_q[3 * n + 1], theta_q[3 * n + 2], uq, vq);
        uv_cols(theta_k[3 * n], theta_k[3 * n + 1], theta_k[3 * n + 2], uk, vk);
        const float* a  = i ? vq : uq;
        const float* bb = j ? vk : uk;
        sG[tid] = a[0] * bb[0] + a[1] * bb[1] + a[2] * bb[2];
    }

    bool isQ = row < NROWS_;
    int r = isQ ? row : row - NROWS_;

    // first 4 of the 64 features, 16B-aligned (row stride 256B)
    float4 xv;
    if (row < 2 * NROWS_)
        xv = *(const float4*)((isQ ? query : key) + (size_t)r * D_);

    __syncthreads();

    if (row >= 2 * NROWS_) return;

    float xs[4] = {xv.x, xv.y, xv.z, xv.w};

    float S[NQ_], C[NQ_];
#pragma unroll
    for (int n = 0; n < NQ_; n++) {
        float t = tanhf(xs[n]);
        sincospif(t, &S[n], &C[n]);
    }

    if (isQ) {
        float out8[8];
#pragma unroll
        for (int n = 0; n < NQ_; n++) {
            out8[2 * n]     = 0.5f * S[n];
            out8[2 * n + 1] = 0.5f * C[n];
        }
        float* d = g_q + (size_t)r * 8;
        *(float4*)(d)     = *(const float4*)(out8);
        *(float4*)(d + 4) = *(const float4*)(out8 + 4);
    } else {
        int b = r >> 10;           // SK_ = 1024
        int s = r & (SK_ - 1);
#pragma unroll
        for (int n = 0; n < NQ_; n++) {
            float G00 = sG[n * 4 + 0], G01 = sG[n * 4 + 1];
            float G10 = sG[n * 4 + 2], G11 = sG[n * 4 + 3];
            g_k[((size_t)(b * 8 + 2 * n))     * SK_ + s] = fmaf(G00, S[n], G01 * C[n]);
            g_k[((size_t)(b * 8 + 2 * n + 1)) * SK_ + s] = fmaf(G10, S[n], G11 * C[n]);
        }
    }
}

// ---------------------------------------------------------------------------
// Phase 2: out[b][q][k] = 0.5 + 0.5 * prod_n (0.5 + q0*k0 + q1*k1)
// Tile: 128 q x 128 k, 256 threads; thread owns 4 k-cols as packed pairs,
// iterates 16 q-rows JAMMED 2 AT A TIME (two independent LDS->FMA->STG
// chains per iteration for 2x ILP).  regs budget 3 blocks/SM (~85).
// ---------------------------------------------------------------------------
#define TQ 128
#define TK 128

__global__ __launch_bounds__(256, 3) void pair_kernel(float* __restrict__ out)
{
    __shared__ __align__(16) float  sq[TQ][8];         // raw q rows
    __shared__ __align__(16) float4 skv[8][TK / 4];    // SoA k tile (G-folded)

    int b  = blockIdx.z;
    int q0 = blockIdx.y * TQ;
    int k0 = blockIdx.x * TK;
    int tid = threadIdx.x;

    // fill skv: 8 comps * 32 float4 = 256 float4 -> one per thread
    {
        int comp = tid >> 5, off = tid & 31;
        skv[comp][off] =
            *(const float4*)(g_k + ((size_t)(b * 8 + comp)) * SK_ + k0 + off * 4);
    }
    // fill sq: TQ*8 floats = 256 float4 -> one per thread
    ((float4*)sq)[tid] =
        ((const float4*)(g_q + (size_t)(b * SQ_ + q0) * 8))[tid];
    __syncthreads();

    int k4 = tid & 31;     // this thread's 4 consecutive k columns
    int qg = tid >> 5;     // q group: rows qg*16 .. qg*16+15

    // k tile: 8 components x (2 packed pairs) in registers
    ulonglong2 kd[8];
#pragma unroll
    for (int j = 0; j < 8; j++)
        kd[j] = *(const ulonglong2*)&skv[j][k4];

    float* obase = out + ((size_t)(b * SQ_ + q0 + qg * 16) * SK_) + k0 + k4 * 4;

#pragma unroll
    for (int rr = 0; rr < 8; rr++) {
        int ra = qg * 16 + 2 * rr;

        // two rows' q vectors (4 warp-uniform LDS.128)
        float4 a0 = *(const float4*)&sq[ra][0];
        float4 a1 = *(const float4*)&sq[ra][4];
        float4 b0 = *(const float4*)&sq[ra + 1][0];
        float4 b1 = *(const float4*)&sq[ra + 1][4];

        unsigned long long qa[8], qb[8];
        qa[0] = f2dup(a0.x); qa[1] = f2dup(a0.y);
        qa[2] = f2dup(a0.z); qa[3] = f2dup(a0.w);
        qa[4] = f2dup(a1.x); qa[5] = f2dup(a1.y);
        qa[6] = f2dup(a1.z); qa[7] = f2dup(a1.w);
        qb[0] = f2dup(b0.x); qb[1] = f2dup(b0.y);
        qb[2] = f2dup(b0.z); qb[3] = f2dup(b0.w);
        qb[4] = f2dup(b1.x); qb[5] = f2dup(b1.y);
        qb[6] = f2dup(b1.z); qb[7] = f2dup(b1.w);

        unsigned long long ta0[NQ_], ta1[NQ_], tb0[NQ_], tb1[NQ_];
#pragma unroll
        for (int n = 0; n < NQ_; n++) {
            ta0[n] = f2fma(qa[2 * n], kd[2 * n].x,
                     f2fma(qa[2 * n + 1], kd[2 * n + 1].x, HALF2_));
            ta1[n] = f2fma(qa[2 * n], kd[2 * n].y,
                     f2fma(qa[2 * n + 1], kd[2 * n + 1].y, HALF2_));
            tb0[n] = f2fma(qb[2 * n], kd[2 * n].x,
                     f2fma(qb[2 * n + 1], kd[2 * n + 1].x, HALF2_));
            tb1[n] = f2fma(qb[2 * n], kd[2 * n].y,
                     f2fma(qb[2 * n + 1], kd[2 * n + 1].y, HALF2_));
        }
        unsigned long long pa0 = f2mul(f2mul(ta0[0], ta0[1]), f2mul(ta0[2], ta0[3]));
        unsigned long long pa1 = f2mul(f2mul(ta1[0], ta1[1]), f2mul(ta1[2], ta1[3]));
        unsigned long long pb0 = f2mul(f2mul(tb0[0], tb0[1]), f2mul(tb0[2], tb0[3]));
        unsigned long long pb1 = f2mul(f2mul(tb1[0], tb1[1]), f2mul(tb1[2], tb1[3]));
        pa0 = f2fma(pa0, HALF2_, HALF2_);
        pa1 = f2fma(pa1, HALF2_, HALF2_);
        pb0 = f2fma(pb0, HALF2_, HALF2_);
        pb1 = f2fma(pb1, HALF2_, HALF2_);

        float* oa = obase + (size_t)(2 * rr) * SK_;
        asm volatile("st.global.v2.b64 [%0], {%1, %2};"
                     :: "l"(oa), "l"(pa0), "l"(pa1) : "memory");
        asm volatile("st.global.v2.b64 [%0], {%1, %2};"
                     :: "l"(oa + SK_), "l"(pb0), "l"(pb1) : "memory");
    }
}

extern "C" void kernel_launch(void* const* d_in, const int* in_sizes, int n_in,
                              void* d_out, int out_size)
{
    const float* query   = (const float*)d_in[0];
    const float* key     = (const float*)d_in[1];
    const float* theta_q = (const float*)d_in[2];
    const float* theta_k = (const float*)d_in[3];
    float* out = (float*)d_out;

    prep_kernel<<<(2 * NROWS_ + 255) / 256, 256>>>(query, key, theta_q, theta_k);

    dim3 grid(SK_ / TK, SQ_ / TQ, B_);
    pair_kernel<<<grid, 256>>>(out);
}

// round 10
// speedup vs baseline: 1.0894x; 1.0024x over previous
#include <cuda_runtime.h>
#include <math.h>

// Problem shape (fixed by setup_inputs): B=8, Sq=Sk=1024, D=64, N_QUBITS=4.
#define B_     8
#define SQ_    1024
#define SK_    1024
#define D_     64
#define NQ_    4

// ---------------------------------------------------------------------------
// packed f32x2 helpers
// ---------------------------------------------------------------------------
__device__ __forceinline__ unsigned long long f2fma(unsigned long long a,
                                                    unsigned long long b,
                                                    unsigned long long c)
{
    unsigned long long d;
    asm("fma.rn.f32x2 %0, %1, %2, %3;" : "=l"(d) : "l"(a), "l"(b), "l"(c));
    return d;
}
__device__ __forceinline__ unsigned long long f2mul(unsigned long long a,
                                                    unsigned long long b)
{
    unsigned long long d;
    asm("mul.rn.f32x2 %0, %1, %2;" : "=l"(d) : "l"(a), "l"(b));
    return d;
}
__device__ __forceinline__ unsigned long long f2dup(float v)
{
    unsigned long long d;
    asm("mov.b64 %0, {%1, %1};" : "=l"(d) : "f"(v));
    return d;
}

#define HALF2_ 0x3F0000003F000000ULL   // {0.5f, 0.5f}

// Bloch-rotation columns of M = Rz(om)*Ry(th)*Rz(phi):  u = M*ex, v = M*ez
__device__ __forceinline__ void uv_cols(float phi, float th, float om,
                                        float u[3], float v[3])
{
    float sp, cp, st, ct, so, co;
    sincosf(phi, &sp, &cp);
    sincosf(th,  &st, &ct);
    sincosf(om,  &so, &co);
    float ax = ct * cp, ay = sp, az = -st * cp;
    u[0] = ax * co - ay * so;
    u[1] = ax * so + ay * co;
    u[2] = az;
    v[0] = st * co;
    v[1] = st * so;
    v[2] = ct;
}

// ---------------------------------------------------------------------------
// FUSED kernel: one launch does everything.
//   out[b][q][k] = 0.5 + 0.5 * prod_n (0.5 + q0*k0 + q1*k1)
// where per-row q = 0.5*(sin pi t, cos pi t), k = G_n * (sin pi t, cos pi t),
// t = tanh(x_n), and G_n is the per-qubit 2x2 Gram matrix of the two Rot
// unitaries (theta only; computed redundantly per block by threads 0..15).
//
// Tile: 128 q x 128 k, 256 threads.
//   prep phase: thread i<128 -> q row i ; i>=128 -> k col i-128.
//   main phase: thread owns 4 k-cols as packed f32x2 pairs, 16 q-rows
//   jammed 2 at a time (two independent LDS->FMA->STG chains).
// ---------------------------------------------------------------------------
#define TQ 128
#define TK 128

__global__ __launch_bounds__(256, 3) void fused_kernel(
    float* __restrict__ out,
    const float* __restrict__ query,
    const float* __restrict__ key,
    const float* __restrict__ theta_q,
    const float* __restrict__ theta_k)
{
    __shared__ __align__(16) float  sq[TQ][8];         // 0.5*(S,C) q rows
    __shared__ __align__(16) float4 skv[8][TK / 4];    // SoA k tile (G-folded)
    __shared__ float sG[16];

    int b  = blockIdx.z;
    int q0 = blockIdx.y * TQ;
    int k0 = blockIdx.x * TK;
    int tid = threadIdx.x;

    // ---- Gram entries (threads 0..15, redundant per block) ----
    if (tid < 16) {
        int n = tid >> 2, i = (tid >> 1) & 1, j = tid & 1;
        float uq[3], vq[3], uk[3], vk[3];
        uv_cols(theta_q[3 * n], theta_q[3 * n + 1], theta_q[3 * n + 2], uq, vq);
        uv_cols(theta_k[3 * n], theta_k[3 * n + 1], theta_k[3 * n + 2], uk, vk);
        const float* a  = i ? vq : uq;
        const float* bb = j ? vk : uk;
        sG[tid] = a[0] * bb[0] + a[1] * bb[1] + a[2] * bb[2];
    }

    // ---- per-row (S,C): thread i<128 -> q row, i>=128 -> k col ----
    bool isQ = tid < TQ;
    int r = isQ ? (b * SQ_ + q0 + tid) : (b * SK_ + k0 + (tid - TQ));
    float4 xv = *(const float4*)((isQ ? query : key) + (size_t)r * D_);
    float xs[4] = {xv.x, xv.y, xv.z, xv.w};

    float S[NQ_], C[NQ_];
#pragma unroll
    for (int n = 0; n < NQ_; n++) {
        float t = tanhf(xs[n]);
        sincospif(t, &S[n], &C[n]);
    }

    if (isQ) {
        // q side needs no G: write now (before the sync)
        float out8[8];
#pragma unroll
        for (int n = 0; n < NQ_; n++) {
            out8[2 * n]     = 0.5f * S[n];
            out8[2 * n + 1] = 0.5f * C[n];
        }
        *(float4*)&sq[tid][0] = *(const float4*)(out8);
        *(float4*)&sq[tid][4] = *(const float4*)(out8 + 4);
    }

    __syncthreads();           // sG ready

    if (!isQ) {
        int s = tid - TQ;      // k column within tile
        float* skf = (float*)skv;   // [comp][TK] floats
#pragma unroll
        for (int n = 0; n < NQ_; n++) {
            float G00 = sG[n * 4 + 0], G01 = sG[n * 4 + 1];
            float G10 = sG[n * 4 + 2], G11 = sG[n * 4 + 3];
            skf[(2 * n)     * TK + s] = fmaf(G00, S[n], G01 * C[n]);
            skf[(2 * n + 1) * TK + s] = fmaf(G10, S[n], G11 * C[n]);
        }
    }
    __syncthreads();           // tiles ready

    int k4 = tid & 31;     // this thread's 4 consecutive k columns
    int qg = tid >> 5;     // q group: rows qg*16 .. qg*16+15

    // k tile: 8 components x (2 packed pairs) in registers
    ulonglong2 kd[8];
#pragma unroll
    for (int j = 0; j < 8; j++)
        kd[j] = *(const ulonglong2*)&skv[j][k4];

    float* obase = out + ((size_t)(b * SQ_ + q0 + qg * 16) * SK_) + k0 + k4 * 4;

#pragma unroll
    for (int rr = 0; rr < 8; rr++) {
        int ra = qg * 16 + 2 * rr;

        // two rows' q vectors (4 warp-uniform LDS.128)
        float4 a0 = *(const float4*)&sq[ra][0];
        float4 a1 = *(const float4*)&sq[ra][4];
        float4 b0 = *(const float4*)&sq[ra + 1][0];
        float4 b1 = *(const float4*)&sq[ra + 1][4];

        unsigned long long qa[8], qb[8];
        qa[0] = f2dup(a0.x); qa[1] = f2dup(a0.y);
        qa[2] = f2dup(a0.z); qa[3] = f2dup(a0.w);
        qa[4] = f2dup(a1.x); qa[5] = f2dup(a1.y);
        qa[6] = f2dup(a1.z); qa[7] = f2dup(a1.w);
        qb[0] = f2dup(b0.x); qb[1] = f2dup(b0.y);
        qb[2] = f2dup(b0.z); qb[3] = f2dup(b0.w);
        qb[4] = f2dup(b1.x); qb[5] = f2dup(b1.y);
        qb[6] = f2dup(b1.z); qb[7] = f2dup(b1.w);

        unsigned long long ta0[NQ_], ta1[NQ_], tb0[NQ_], tb1[NQ_];
#pragma unroll
        for (int n = 0; n < NQ_; n++) {
            ta0[n] = f2fma(qa[2 * n], kd[2 * n].x,
                     f2fma(qa[2 * n + 1], kd[2 * n + 1].x, HALF2_));
            ta1[n] = f2fma(qa[2 * n], kd[2 * n].y,
                     f2fma(qa[2 * n + 1], kd[2 * n + 1].y, HALF2_));
            tb0[n] = f2fma(qb[2 * n], kd[2 * n].x,
                     f2fma(qb[2 * n + 1], kd[2 * n + 1].x, HALF2_));
            tb1[n] = f2fma(qb[2 * n], kd[2 * n].y,
                     f2fma(qb[2 * n + 1], kd[2 * n + 1].y, HALF2_));
        }
        unsigned long long pa0 = f2mul(f2mul(ta0[0], ta0[1]), f2mul(ta0[2], ta0[3]));
        unsigned long long pa1 = f2mul(f2mul(ta1[0], ta1[1]), f2mul(ta1[2], ta1[3]));
        unsigned long long pb0 = f2mul(f2mul(tb0[0], tb0[1]), f2mul(tb0[2], tb0[3]));
        unsigned long long pb1 = f2mul(f2mul(tb1[0], tb1[1]), f2mul(tb1[2], tb1[3]));
        pa0 = f2fma(pa0, HALF2_, HALF2_);
        pa1 = f2fma(pa1, HALF2_, HALF2_);
        pb0 = f2fma(pb0, HALF2_, HALF2_);
        pb1 = f2fma(pb1, HALF2_, HALF2_);

        float* oa = obase + (size_t)(2 * rr) * SK_;
        asm volatile("st.global.v2.b64 [%0], {%1, %2};"
                     :: "l"(oa), "l"(pa0), "l"(pa1) : "memory");
        asm volatile("st.global.v2.b64 [%0], {%1, %2};"
                     :: "l"(oa + SK_), "l"(pb0), "l"(pb1) : "memory");
    }
}

extern "C" void kernel_launch(void* const* d_in, const int* in_sizes, int n_in,
                              void* d_out, int out_size)
{
    const float* query   = (const float*)d_in[0];
    const float* key     = (const float*)d_in[1];
    const float* theta_q = (const float*)d_in[2];
    const float* theta_k = (const float*)d_in[3];
    float* out = (float*)d_out;

    dim3 grid(SK_ / TK, SQ_ / TQ, B_);
    fused_kernel<<<grid, 256>>>(out, query, key, theta_q, theta_k);
}

// round 11
// speedup vs baseline: 1.1163x; 1.0248x over previous
#include <cuda_runtime.h>
#include <math.h>

// Problem shape (fixed by setup_inputs): B=8, Sq=Sk=1024, D=64, N_QUBITS=4.
#define B_     8
#define SQ_    1024
#define SK_    1024
#define D_     64
#define NQ_    4

// ---------------------------------------------------------------------------
// packed f32x2 helpers
// ---------------------------------------------------------------------------
__device__ __forceinline__ unsigned long long f2fma(unsigned long long a,
                                                    unsigned long long b,
                                                    unsigned long long c)
{
    unsigned long long d;
    asm("fma.rn.f32x2 %0, %1, %2, %3;" : "=l"(d) : "l"(a), "l"(b), "l"(c));
    return d;
}
__device__ __forceinline__ unsigned long long f2mul(unsigned long long a,
                                                    unsigned long long b)
{
    unsigned long long d;
    asm("mul.rn.f32x2 %0, %1, %2;" : "=l"(d) : "l"(a), "l"(b));
    return d;
}
__device__ __forceinline__ unsigned long long f2dup(float v)
{
    unsigned long long d;
    asm("mov.b64 %0, {%1, %1};" : "=l"(d) : "f"(v));
    return d;
}

#define HALF2_ 0x3F0000003F000000ULL   // {0.5f, 0.5f}
#define PI_    3.14159265358979323846f

// fast tanh: 1 - 2/(e^{2x}+1).  MUFU ex2 + rcp; saturates correctly at +-1.
__device__ __forceinline__ float fast_tanh(float x)
{
    float e = __expf(2.0f * x);
    return 1.0f - __fdividef(2.0f, e + 1.0f);
}

// Bloch-rotation columns of M = Rz(om)*Ry(th)*Rz(phi):  u = M*ex, v = M*ez
// (fast __sincosf: thetas are O(0.1), approx error ~1e-7 — far under tol)
__device__ __forceinline__ void uv_cols(float phi, float th, float om,
                                        float u[3], float v[3])
{
    float sp, cp, st, ct, so, co;
    __sincosf(phi, &sp, &cp);
    __sincosf(th,  &st, &ct);
    __sincosf(om,  &so, &co);
    float ax = ct * cp, ay = sp, az = -st * cp;
    u[0] = ax * co - ay * so;
    u[1] = ax * so + ay * co;
    u[2] = az;
    v[0] = st * co;
    v[1] = st * so;
    v[2] = ct;
}

// ---------------------------------------------------------------------------
// FUSED kernel: one launch does everything.
//   out[b][q][k] = 0.5 + 0.5 * prod_n (0.5 + q0*k0 + q1*k1)
// where per-row q = 0.5*(sin pi t, cos pi t), k = G_n * (sin pi t, cos pi t),
// t = tanh(x_n), and G_n is the per-qubit 2x2 Gram matrix of the two Rot
// unitaries (theta only; computed redundantly per block by threads 0..15).
// All transcendentals use fast MUFU approximations (precision headroom 1e3x).
//
// Tile: 128 q x 128 k, 256 threads.
//   prep phase: thread i<128 -> q row i ; i>=128 -> k col i-128.
//   main phase: thread owns 4 k-cols as packed f32x2 pairs, 16 q-rows
//   jammed 2 at a time (two independent LDS->FMA->STG chains).
// ---------------------------------------------------------------------------
#define TQ 128
#define TK 128

__global__ __launch_bounds__(256, 3) void fused_kernel(
    float* __restrict__ out,
    const float* __restrict__ query,
    const float* __restrict__ key,
    const float* __restrict__ theta_q,
    const float* __restrict__ theta_k)
{
    __shared__ __align__(16) float  sq[TQ][8];         // 0.5*(S,C) q rows
    __shared__ __align__(16) float4 skv[8][TK / 4];    // SoA k tile (G-folded)
    __shared__ float sG[16];

    int b  = blockIdx.z;
    int q0 = blockIdx.y * TQ;
    int k0 = blockIdx.x * TK;
    int tid = threadIdx.x;

    // ---- Gram entries (threads 0..15, redundant per block) ----
    if (tid < 16) {
        int n = tid >> 2, i = (tid >> 1) & 1, j = tid & 1;
        float uq[3], vq[3], uk[3], vk[3];
        uv_cols(theta_q[3 * n], theta_q[3 * n + 1], theta_q[3 * n + 2], uq, vq);
        uv_cols(theta_k[3 * n], theta_k[3 * n + 1], theta_k[3 * n + 2], uk, vk);
        const float* a  = i ? vq : uq;
        const float* bb = j ? vk : uk;
        sG[tid] = a[0] * bb[0] + a[1] * bb[1] + a[2] * bb[2];
    }

    // ---- per-row (S,C): thread i<128 -> q row, i>=128 -> k col ----
    bool isQ = tid < TQ;
    int r = isQ ? (b * SQ_ + q0 + tid) : (b * SK_ + k0 + (tid - TQ));
    float4 xv = *(const float4*)((isQ ? query : key) + (size_t)r * D_);
    float xs[4] = {xv.x, xv.y, xv.z, xv.w};

    float S[NQ_], C[NQ_];
#pragma unroll
    for (int n = 0; n < NQ_; n++) {
        float t = fast_tanh(xs[n]);
        __sincosf(t * PI_, &S[n], &C[n]);
    }

    if (isQ) {
        // q side needs no G: write now (before the sync)
        float out8[8];
#pragma unroll
        for (int n = 0; n < NQ_; n++) {
            out8[2 * n]     = 0.5f * S[n];
            out8[2 * n + 1] = 0.5f * C[n];
        }
        *(float4*)&sq[tid][0] = *(const float4*)(out8);
        *(float4*)&sq[tid][4] = *(const float4*)(out8 + 4);
    }

    __syncthreads();           // sG ready

    if (!isQ) {
        int s = tid - TQ;      // k column within tile
        float* skf = (float*)skv;   // [comp][TK] floats
#pragma unroll
        for (int n = 0; n < NQ_; n++) {
            float G00 = sG[n * 4 + 0], G01 = sG[n * 4 + 1];
            float G10 = sG[n * 4 + 2], G11 = sG[n * 4 + 3];
            skf[(2 * n)     * TK + s] = fmaf(G00, S[n], G01 * C[n]);
            skf[(2 * n + 1) * TK + s] = fmaf(G10, S[n], G11 * C[n]);
        }
    }
    __syncthreads();           // tiles ready

    int k4 = tid & 31;     // this thread's 4 consecutive k columns
    int qg = tid >> 5;     // q group: rows qg*16 .. qg*16+15

    // k tile: 8 components x (2 packed pairs) in registers
    ulonglong2 kd[8];
#pragma unroll
    for (int j = 0; j < 8; j++)
        kd[j] = *(const ulonglong2*)&skv[j][k4];

    float* obase = out + ((size_t)(b * SQ_ + q0 + qg * 16) * SK_) + k0 + k4 * 4;

#pragma unroll
    for (int rr = 0; rr < 8; rr++) {
        int ra = qg * 16 + 2 * rr;

        // two rows' q vectors (4 warp-uniform LDS.128)
        float4 a0 = *(const float4*)&sq[ra][0];
        float4 a1 = *(const float4*)&sq[ra][4];
        float4 b0 = *(const float4*)&sq[ra + 1][0];
        float4 b1 = *(const float4*)&sq[ra + 1][4];

        unsigned long long qa[8], qb[8];
        qa[0] = f2dup(a0.x); qa[1] = f2dup(a0.y);
        qa[2] = f2dup(a0.z); qa[3] = f2dup(a0.w);
        qa[4] = f2dup(a1.x); qa[5] = f2dup(a1.y);
        qa[6] = f2dup(a1.z); qa[7] = f2dup(a1.w);
        qb[0] = f2dup(b0.x); qb[1] = f2dup(b0.y);
        qb[2] = f2dup(b0.z); qb[3] = f2dup(b0.w);
        qb[4] = f2dup(b1.x); qb[5] = f2dup(b1.y);
        qb[6] = f2dup(b1.z); qb[7] = f2dup(b1.w);

        unsigned long long ta0[NQ_], ta1[NQ_], tb0[NQ_], tb1[NQ_];
#pragma unroll
        for (int n = 0; n < NQ_; n++) {
            ta0[n] = f2fma(qa[2 * n], kd[2 * n].x,
                     f2fma(qa[2 * n + 1], kd[2 * n + 1].x, HALF2_));
            ta1[n] = f2fma(qa[2 * n], kd[2 * n].y,
                     f2fma(qa[2 * n + 1], kd[2 * n + 1].y, HALF2_));
            tb0[n] = f2fma(qb[2 * n], kd[2 * n].x,
                     f2fma(qb[2 * n + 1], kd[2 * n + 1].x, HALF2_));
            tb1[n] = f2fma(qb[2 * n], kd[2 * n].y,
                     f2fma(qb[2 * n + 1], kd[2 * n + 1].y, HALF2_));
        }
        unsigned long long pa0 = f2mul(f2mul(ta0[0], ta0[1]), f2mul(ta0[2], ta0[3]));
        unsigned long long pa1 = f2mul(f2mul(ta1[0], ta1[1]), f2mul(ta1[2], ta1[3]));
        unsigned long long pb0 = f2mul(f2mul(tb0[0], tb0[1]), f2mul(tb0[2], tb0[3]));
        unsigned long long pb1 = f2mul(f2mul(tb1[0], tb1[1]), f2mul(tb1[2], tb1[3]));
        pa0 = f2fma(pa0, HALF2_, HALF2_);
        pa1 = f2fma(pa1, HALF2_, HALF2_);
        pb0 = f2fma(pb0, HALF2_, HALF2_);
        pb1 = f2fma(pb1, HALF2_, HALF2_);

        float* oa = obase + (size_t)(2 * rr) * SK_;
        asm volatile("st.global.v2.b64 [%0], {%1, %2};"
                     :: "l"(oa), "l"(pa0), "l"(pa1) : "memory");
        asm volatile("st.global.v2.b64 [%0], {%1, %2};"
                     :: "l"(oa + SK_), "l"(pb0), "l"(pb1) : "memory");
    }
}

extern "C" void kernel_launch(void* const* d_in, const int* in_sizes, int n_in,
                              void* d_out, int out_size)
{
    const float* query   = (const float*)d_in[0];
    const float* key     = (const float*)d_in[1];
    const float* theta_q = (const float*)d_in[2];
    const float* theta_k = (const float*)d_in[3];
    float* out = (float*)d_out;

    dim3 grid(SK_ / TK, SQ_ / TQ, B_);
    fused_kernel<<<grid, 256>>>(out, query, key, theta_q, theta_k);
}

// round 12
// speedup vs baseline: 1.1714x; 1.0494x over previous
#include <cuda_runtime.h>
#include <math.h>

// Problem shape (fixed by setup_inputs): B=8, Sq=Sk=1024, D=64, N_QUBITS=4.
#define B_     8
#define SQ_    1024
#define SK_    1024
#define D_     64
#define NQ_    4

// ---------------------------------------------------------------------------
// packed f32x2 helpers
// ---------------------------------------------------------------------------
__device__ __forceinline__ unsigned long long f2fma(unsigned long long a,
                                                    unsigned long long b,
                                                    unsigned long long c)
{
    unsigned long long d;
    asm("fma.rn.f32x2 %0, %1, %2, %3;" : "=l"(d) : "l"(a), "l"(b), "l"(c));
    return d;
}
__device__ __forceinline__ unsigned long long f2mul(unsigned long long a,
                                                    unsigned long long b)
{
    unsigned long long d;
    asm("mul.rn.f32x2 %0, %1, %2;" : "=l"(d) : "l"(a), "l"(b));
    return d;
}
__device__ __forceinline__ unsigned long long f2dup(float v)
{
    unsigned long long d;
    asm("mov.b64 %0, {%1, %1};" : "=l"(d) : "f"(v));
    return d;
}

#define HALF2_ 0x3F0000003F000000ULL   // {0.5f, 0.5f}
#define PI_    3.14159265358979323846f

// fast tanh: 1 - 2/(e^{2x}+1).  MUFU ex2 + rcp; saturates correctly at +-1.
__device__ __forceinline__ float fast_tanh(float x)
{
    float e = __expf(2.0f * x);
    return 1.0f - __fdividef(2.0f, e + 1.0f);
}

// Bloch-rotation columns of M = Rz(om)*Ry(th)*Rz(phi):  u = M*ex, v = M*ez
__device__ __forceinline__ void uv_cols(float phi, float th, float om,
                                        float u[3], float v[3])
{
    float sp, cp, st, ct, so, co;
    __sincosf(phi, &sp, &cp);
    __sincosf(th,  &st, &ct);
    __sincosf(om,  &so, &co);
    float ax = ct * cp, ay = sp, az = -st * cp;
    u[0] = ax * co - ay * so;
    u[1] = ax * so + ay * co;
    u[2] = az;
    v[0] = st * co;
    v[1] = st * so;
    v[2] = ct;
}

// ---------------------------------------------------------------------------
// FUSED kernel, single __syncthreads:
//   out[b][q][k] = 0.5 + 0.5 * prod_n (0.5 + q.(G_n k))
// Per-row q = 0.5*(sin pi t, cos pi t), raw k = (sin pi t, cos pi t),
// t = tanh(x_n).  G_n (per-qubit 2x2 Gram of the two Rot unitaries) is
// computed by threads 0..15 into smem (duplicated pairs) and applied ONCE to
// each thread's register-resident k-tile after the single barrier — so the
// serial Gram chain hides behind everyone's row-trig instead of a barrier.
//
// Tile: 128 q x 128 k, 256 threads.
//   prep: thread i<128 -> q row i ; i>=128 -> raw k col i-128.
//   main: thread owns 4 k-cols as packed f32x2 pairs, 16 q-rows jammed 2
//   at a time (two independent LDS->FMA->STG chains).
// ---------------------------------------------------------------------------
#define TQ 128
#define TK 128

__global__ __launch_bounds__(256, 3) void fused_kernel(
    float* __restrict__ out,
    const float* __restrict__ query,
    const float* __restrict__ key,
    const float* __restrict__ theta_q,
    const float* __restrict__ theta_k)
{
    __shared__ __align__(16) float  sq[TQ][8];         // 0.5*(S,C) q rows
    __shared__ __align__(16) float4 skv[8][TK / 4];    // SoA RAW k tile
    __shared__ __align__(8)  float2 sGd[16];           // {g,g} duplicated

    int b  = blockIdx.z;
    int q0 = blockIdx.y * TQ;
    int k0 = blockIdx.x * TK;
    int tid = threadIdx.x;

    // ---- issue the row LDG first (overlaps the Gram chain below) ----
    bool isQ = tid < TQ;
    int r = isQ ? (b * SQ_ + q0 + tid) : (b * SK_ + k0 + (tid - TQ));
    float4 xv = *(const float4*)((isQ ? query : key) + (size_t)r * D_);

    // ---- Gram entries (threads 0..15, redundant per block) ----
    if (tid < 16) {
        int n = tid >> 2, i = (tid >> 1) & 1, j = tid & 1;
        float uq[3], vq[3], uk[3], vk[3];
        uv_cols(theta_q[3 * n], theta_q[3 * n + 1], theta_q[3 * n + 2], uq, vq);
        uv_cols(theta_k[3 * n], theta_k[3 * n + 1], theta_k[3 * n + 2], uk, vk);
        const float* a  = i ? vq : uq;
        const float* bb = j ? vk : uk;
        float g = a[0] * bb[0] + a[1] * bb[1] + a[2] * bb[2];
        sGd[tid] = make_float2(g, g);
    }

    // ---- per-row (S,C) ----
    float xs[4] = {xv.x, xv.y, xv.z, xv.w};
    float S[NQ_], C[NQ_];
#pragma unroll
    for (int n = 0; n < NQ_; n++) {
        float t = fast_tanh(xs[n]);
        __sincosf(t * PI_, &S[n], &C[n]);
    }

    if (isQ) {
        float out8[8];
#pragma unroll
        for (int n = 0; n < NQ_; n++) {
            out8[2 * n]     = 0.5f * S[n];
            out8[2 * n + 1] = 0.5f * C[n];
        }
        *(float4*)&sq[tid][0] = *(const float4*)(out8);
        *(float4*)&sq[tid][4] = *(const float4*)(out8 + 4);
    } else {
        int s = tid - TQ;      // k column within tile (raw S,C — no G yet)
        float* skf = (float*)skv;   // [comp][TK] floats
#pragma unroll
        for (int n = 0; n < NQ_; n++) {
            skf[(2 * n)     * TK + s] = S[n];
            skf[(2 * n + 1) * TK + s] = C[n];
        }
    }
    __syncthreads();           // sGd + both tiles ready (single barrier)

    int k4 = tid & 31;     // this thread's 4 consecutive k columns
    int qg = tid >> 5;     // q group: rows qg*16 .. qg*16+15

    // raw k tile -> registers, then fold G once (16 packed ops, one-time)
    ulonglong2 kd[8];
#pragma unroll
    for (int j = 0; j < 8; j++)
        kd[j] = *(const ulonglong2*)&skv[j][k4];

#pragma unroll
    for (int n = 0; n < NQ_; n++) {
        unsigned long long g00 = *(const unsigned long long*)&sGd[n * 4 + 0];
        unsigned long long g01 = *(const unsigned long long*)&sGd[n * 4 + 1];
        unsigned long long g10 = *(const unsigned long long*)&sGd[n * 4 + 2];
        unsigned long long g11 = *(const unsigned long long*)&sGd[n * 4 + 3];
        ulonglong2 Sv = kd[2 * n], Cv = kd[2 * n + 1];
        kd[2 * n].x     = f2fma(g00, Sv.x, f2mul(g01, Cv.x));
        kd[2 * n].y     = f2fma(g00, Sv.y, f2mul(g01, Cv.y));
        kd[2 * n + 1].x = f2fma(g10, Sv.x, f2mul(g11, Cv.x));
        kd[2 * n + 1].y = f2fma(g10, Sv.y, f2mul(g11, Cv.y));
    }

    float* obase = out + ((size_t)(b * SQ_ + q0 + qg * 16) * SK_) + k0 + k4 * 4;

#pragma unroll
    for (int rr = 0; rr < 8; rr++) {
        int ra = qg * 16 + 2 * rr;

        // two rows' q vectors (4 warp-uniform LDS.128)
        float4 a0 = *(const float4*)&sq[ra][0];
        float4 a1 = *(const float4*)&sq[ra][4];
        float4 b0 = *(const float4*)&sq[ra + 1][0];
        float4 b1 = *(const float4*)&sq[ra + 1][4];

        unsigned long long qa[8], qb[8];
        qa[0] = f2dup(a0.x); qa[1] = f2dup(a0.y);
        qa[2] = f2dup(a0.z); qa[3] = f2dup(a0.w);
        qa[4] = f2dup(a1.x); qa[5] = f2dup(a1.y);
        qa[6] = f2dup(a1.z); qa[7] = f2dup(a1.w);
        qb[0] = f2dup(b0.x); qb[1] = f2dup(b0.y);
        qb[2] = f2dup(b0.z); qb[3] = f2dup(b0.w);
        qb[4] = f2dup(b1.x); qb[5] = f2dup(b1.y);
        qb[6] = f2dup(b1.z); qb[7] = f2dup(b1.w);

        unsigned long long ta0[NQ_], ta1[NQ_], tb0[NQ_], tb1[NQ_];
#pragma unroll
        for (int n = 0; n < NQ_; n++) {
            ta0[n] = f2fma(qa[2 * n], kd[2 * n].x,
                     f2fma(qa[2 * n + 1], kd[2 * n + 1].x, HALF2_));
            ta1[n] = f2fma(qa[2 * n], kd[2 * n].y,
                     f2fma(qa[2 * n + 1], kd[2 * n + 1].y, HALF2_));
            tb0[n] = f2fma(qb[2 * n], kd[2 * n].x,
                     f2fma(qb[2 * n + 1], kd[2 * n + 1].x, HALF2_));
            tb1[n] = f2fma(qb[2 * n], kd[2 * n].y,
                     f2fma(qb[2 * n + 1], kd[2 * n + 1].y, HALF2_));
        }
        unsigned long long pa0 = f2mul(f2mul(ta0[0], ta0[1]), f2mul(ta0[2], ta0[3]));
        unsigned long long pa1 = f2mul(f2mul(ta1[0], ta1[1]), f2mul(ta1[2], ta1[3]));
        unsigned long long pb0 = f2mul(f2mul(tb0[0], tb0[1]), f2mul(tb0[2], tb0[3]));
        unsigned long long pb1 = f2mul(f2mul(tb1[0], tb1[1]), f2mul(tb1[2], tb1[3]));
        pa0 = f2fma(pa0, HALF2_, HALF2_);
        pa1 = f2fma(pa1, HALF2_, HALF2_);
        pb0 = f2fma(pb0, HALF2_, HALF2_);
        pb1 = f2fma(pb1, HALF2_, HALF2_);

        float* oa = obase + (size_t)(2 * rr) * SK_;
        asm volatile("st.global.v2.b64 [%0], {%1, %2};"
                     :: "l"(oa), "l"(pa0), "l"(pa1) : "memory");
        asm volatile("st.global.v2.b64 [%0], {%1, %2};"
                     :: "l"(oa + SK_), "l"(pb0), "l"(pb1) : "memory");
    }
}

extern "C" void kernel_launch(void* const* d_in, const int* in_sizes, int n_in,
                              void* d_out, int out_size)
{
    const float* query   = (const float*)d_in[0];
    const float* key     = (const float*)d_in[1];
    const float* theta_q = (const float*)d_in[2];
    const float* theta_k = (const float*)d_in[3];
    float* out = (float*)d_out;

    dim3 grid(SK_ / TK, SQ_ / TQ, B_);
    fused_kernel<<<grid, 256>>>(out, query, key, theta_q, theta_k);
}

// round 13
// speedup vs baseline: 1.2776x; 1.0907x over previous
#include <cuda_runtime.h>
#include <math.h>

// Problem shape (fixed by setup_inputs): B=8, Sq=Sk=1024, D=64, N_QUBITS=4.
#define B_     8
#define SQ_    1024
#define SK_    1024
#define D_     64
#define NQ_    4

// ---------------------------------------------------------------------------
// packed f32x2 helpers
// ---------------------------------------------------------------------------
__device__ __forceinline__ unsigned long long f2fma(unsigned long long a,
                                                    unsigned long long b,
                                                    unsigned long long c)
{
    unsigned long long d;
    asm("fma.rn.f32x2 %0, %1, %2, %3;" : "=l"(d) : "l"(a), "l"(b), "l"(c));
    return d;
}
__device__ __forceinline__ unsigned long long f2mul(unsigned long long a,
                                                    unsigned long long b)
{
    unsigned long long d;
    asm("mul.rn.f32x2 %0, %1, %2;" : "=l"(d) : "l"(a), "l"(b));
    return d;
}
__device__ __forceinline__ unsigned long long f2dup(float v)
{
    unsigned long long d;
    asm("mov.b64 %0, {%1, %1};" : "=l"(d) : "f"(v));
    return d;
}

#define HALF2_ 0x3F0000003F000000ULL   // {0.5f, 0.5f}
#define PI_    3.14159265358979323846f

// fast tanh: 1 - 2/(e^{2x}+1).  MUFU ex2 + rcp; saturates correctly at +-1.
__device__ __forceinline__ float fast_tanh(float x)
{
    float e = __expf(2.0f * x);
    return 1.0f - __fdividef(2.0f, e + 1.0f);
}

// Bloch-rotation columns of M = Rz(om)*Ry(th)*Rz(phi):  u = M*ex, v = M*ez
__device__ __forceinline__ void uv_cols(float phi, float th, float om,
                                        float u[3], float v[3])
{
    float sp, cp, st, ct, so, co;
    __sincosf(phi, &sp, &cp);
    __sincosf(th,  &st, &ct);
    __sincosf(om,  &so, &co);
    float ax = ct * cp, ay = sp, az = -st * cp;
    u[0] = ax * co - ay * so;
    u[1] = ax * so + ay * co;
    u[2] = az;
    v[0] = st * co;
    v[1] = st * so;
    v[2] = ct;
}

// per-row trig: t = tanh(x), (S,C) = sincos(pi t)
__device__ __forceinline__ void row_sc(float4 xv, float S[NQ_], float C[NQ_])
{
    float xs[4] = {xv.x, xv.y, xv.z, xv.w};
#pragma unroll
    for (int n = 0; n < NQ_; n++) {
        float t = fast_tanh(xs[n]);
        __sincosf(t * PI_, &S[n], &C[n]);
    }
}

// ---------------------------------------------------------------------------
// FUSED kernel, single __syncthreads, 256-q-row tile (single wave: 256 blocks)
//   out[b][q][k] = 0.5 + 0.5 * prod_n (0.5 + q.(G_n k))
// prep: every thread computes q row `tid`; threads 128..255 also compute raw
// k col `tid-128`; threads 0..15 also compute the 16 Gram entries.
// main: thread owns 4 k-cols as packed f32x2 pairs (G folded once in regs),
// iterates 32 q-rows jammed 2 at a time.
// ---------------------------------------------------------------------------
#define TQ 256
#define TK 128

__global__ __launch_bounds__(256, 3) void fused_kernel(
    float* __restrict__ out,
    const float* __restrict__ query,
    const float* __restrict__ key,
    const float* __restrict__ theta_q,
    const float* __restrict__ theta_k)
{
    __shared__ __align__(16) float  sq[TQ][8];         // 0.5*(S,C) q rows
    __shared__ __align__(16) float4 skv[8][TK / 4];    // SoA RAW k tile
    __shared__ __align__(8)  float2 sGd[16];           // {g,g} duplicated

    int b  = blockIdx.z;
    int q0 = blockIdx.y * TQ;
    int k0 = blockIdx.x * TK;
    int tid = threadIdx.x;

    // ---- issue row LDGs first (overlap the Gram chain) ----
    float4 xq = *(const float4*)(query + (size_t)(b * SQ_ + q0 + tid) * D_);
    bool hasK = tid >= 128;
    float4 xk;
    if (hasK)
        xk = *(const float4*)(key + (size_t)(b * SK_ + k0 + (tid - 128)) * D_);

    // ---- Gram entries (threads 0..15, redundant per block) ----
    if (tid < 16) {
        int n = tid >> 2, i = (tid >> 1) & 1, j = tid & 1;
        float uq[3], vq[3], uk[3], vk[3];
        uv_cols(theta_q[3 * n], theta_q[3 * n + 1], theta_q[3 * n + 2], uq, vq);
        uv_cols(theta_k[3 * n], theta_k[3 * n + 1], theta_k[3 * n + 2], uk, vk);
        const float* a  = i ? vq : uq;
        const float* bb = j ? vk : uk;
        float g = a[0] * bb[0] + a[1] * bb[1] + a[2] * bb[2];
        sGd[tid] = make_float2(g, g);
    }

    // ---- q row (every thread) ----
    {
        float S[NQ_], C[NQ_];
        row_sc(xq, S, C);
        float out8[8];
#pragma unroll
        for (int n = 0; n < NQ_; n++) {
            out8[2 * n]     = 0.5f * S[n];
            out8[2 * n + 1] = 0.5f * C[n];
        }
        *(float4*)&sq[tid][0] = *(const float4*)(out8);
        *(float4*)&sq[tid][4] = *(const float4*)(out8 + 4);
    }

    // ---- raw k col (threads 128..255) ----
    if (hasK) {
        float S[NQ_], C[NQ_];
        row_sc(xk, S, C);
        int s = tid - 128;
        float* skf = (float*)skv;   // [comp][TK] floats
#pragma unroll
        for (int n = 0; n < NQ_; n++) {
            skf[(2 * n)     * TK + s] = S[n];
            skf[(2 * n + 1) * TK + s] = C[n];
        }
    }
    __syncthreads();           // sGd + both tiles ready (single barrier)

    int k4 = tid & 31;     // this thread's 4 consecutive k columns
    int qg = tid >> 5;     // q group: rows qg*32 .. qg*32+31

    // raw k tile -> registers, fold G once (16 packed ops, one-time)
    ulonglong2 kd[8];
#pragma unroll
    for (int j = 0; j < 8; j++)
        kd[j] = *(const ulonglong2*)&skv[j][k4];

#pragma unroll
    for (int n = 0; n < NQ_; n++) {
        unsigned long long g00 = *(const unsigned long long*)&sGd[n * 4 + 0];
        unsigned long long g01 = *(const unsigned long long*)&sGd[n * 4 + 1];
        unsigned long long g10 = *(const unsigned long long*)&sGd[n * 4 + 2];
        unsigned long long g11 = *(const unsigned long long*)&sGd[n * 4 + 3];
        ulonglong2 Sv = kd[2 * n], Cv = kd[2 * n + 1];
        kd[2 * n].x     = f2fma(g00, Sv.x, f2mul(g01, Cv.x));
        kd[2 * n].y     = f2fma(g00, Sv.y, f2mul(g01, Cv.y));
        kd[2 * n + 1].x = f2fma(g10, Sv.x, f2mul(g11, Cv.x));
        kd[2 * n + 1].y = f2fma(g10, Sv.y, f2mul(g11, Cv.y));
    }

    float* obase = out + ((size_t)(b * SQ_ + q0 + qg * 32) * SK_) + k0 + k4 * 4;

#pragma unroll
    for (int rr = 0; rr < 16; rr++) {
        int ra = qg * 32 + 2 * rr;

        // two rows' q vectors (4 warp-uniform LDS.128)
        float4 a0 = *(const float4*)&sq[ra][0];
        float4 a1 = *(const float4*)&sq[ra][4];
        float4 b0 = *(const float4*)&sq[ra + 1][0];
        float4 b1 = *(const float4*)&sq[ra + 1][4];

        unsigned long long qa[8], qb[8];
        qa[0] = f2dup(a0.x); qa[1] = f2dup(a0.y);
        qa[2] = f2dup(a0.z); qa[3] = f2dup(a0.w);
        qa[4] = f2dup(a1.x); qa[5] = f2dup(a1.y);
        qa[6] = f2dup(a1.z); qa[7] = f2dup(a1.w);
        qb[0] = f2dup(b0.x); qb[1] = f2dup(b0.y);
        qb[2] = f2dup(b0.z); qb[3] = f2dup(b0.w);
        qb[4] = f2dup(b1.x); qb[5] = f2dup(b1.y);
        qb[6] = f2dup(b1.z); qb[7] = f2dup(b1.w);

        unsigned long long ta0[NQ_], ta1[NQ_], tb0[NQ_], tb1[NQ_];
#pragma unroll
        for (int n = 0; n < NQ_; n++) {
            ta0[n] = f2fma(qa[2 * n], kd[2 * n].x,
                     f2fma(qa[2 * n + 1], kd[2 * n + 1].x, HALF2_));
            ta1[n] = f2fma(qa[2 * n], kd[2 * n].y,
                     f2fma(qa[2 * n + 1], kd[2 * n + 1].y, HALF2_));
            tb0[n] = f2fma(qb[2 * n], kd[2 * n].x,
                     f2fma(qb[2 * n + 1], kd[2 * n + 1].x, HALF2_));
            tb1[n] = f2fma(qb[2 * n], kd[2 * n].y,
                     f2fma(qb[2 * n + 1], kd[2 * n + 1].y, HALF2_));
        }
        unsigned long long pa0 = f2mul(f2mul(ta0[0], ta0[1]), f2mul(ta0[2], ta0[3]));
        unsigned long long pa1 = f2mul(f2mul(ta1[0], ta1[1]), f2mul(ta1[2], ta1[3]));
        unsigned long long pb0 = f2mul(f2mul(tb0[0], tb0[1]), f2mul(tb0[2], tb0[3]));
        unsigned long long pb1 = f2mul(f2mul(tb1[0], tb1[1]), f2mul(tb1[2], tb1[3]));
        pa0 = f2fma(pa0, HALF2_, HALF2_);
        pa1 = f2fma(pa1, HALF2_, HALF2_);
        pb0 = f2fma(pb0, HALF2_, HALF2_);
        pb1 = f2fma(pb1, HALF2_, HALF2_);

        float* oa = obase + (size_t)(2 * rr) * SK_;
        asm volatile("st.global.v2.b64 [%0], {%1, %2};"
                     :: "l"(oa), "l"(pa0), "l"(pa1) : "memory");
        asm volatile("st.global.v2.b64 [%0], {%1, %2};"
                     :: "l"(oa + SK_), "l"(pb0), "l"(pb1) : "memory");
    }
}

extern "C" void kernel_launch(void* const* d_in, const int* in_sizes, int n_in,
                              void* d_out, int out_size)
{
    const float* query   = (const float*)d_in[0];
    const float* key     = (const float*)d_in[1];
    const float* theta_q = (const float*)d_in[2];
    const float* theta_k = (const float*)d_in[3];
    float* out = (float*)d_out;

    dim3 grid(SK_ / TK, SQ_ / TQ, B_);
    fused_kernel<<<grid, 256>>>(out, query, key, theta_q, theta_k);
}